// round 6
// baseline (speedup 1.0000x reference)
#include <cuda_runtime.h>
#include <cuda_fp16.h>
#include <math.h>

// ---------------------------------------------------------------------------
// Problem constants
// ---------------------------------------------------------------------------
constexpr int Bb   = 2;
constexpr int Cc   = 96;
constexpr int HEADS= 6;
constexpr int HID  = 192;
constexpr int TOK  = Bb * 256 * 256;          // 131072 tokens

// ---------------------------------------------------------------------------
// Static device scratch
// ---------------------------------------------------------------------------
__device__ float g_lnx [TOK * Cc];
__device__ float g_lnr [TOK * Cc];
__device__ float g_qkvx[TOK * 288];
__device__ float g_qkvr[TOK * 288];
__device__ float g_y   [TOK * Cc];
__device__ float g_tmp [TOK * Cc];
__device__ float g_x2  [TOK * Cc];
__device__ float g_h1  [TOK * HID];
__device__ float g_h2  [TOK * HID];

#define DEV __device__ __forceinline__

DEV float gelu_f(float v) { return 0.5f * v * (1.0f + erff(v * 0.70710678118654752f)); }

DEV unsigned packh2(float lo, float hi) {
    __half2 h = __floats2half2_rn(lo, hi);          // lo -> .x (low 16 bits)
    return *reinterpret_cast<unsigned*>(&h);
}

// D += A(16x16, f16, row) * B(16x8, f16, col), fp32 accum
DEV void mma_f16(float* c, const unsigned* a, const unsigned* b) {
    asm("mma.sync.aligned.m16n8k16.row.col.f32.f16.f16.f32 "
        "{%0,%1,%2,%3}, {%4,%5,%6,%7}, {%8,%9}, {%0,%1,%2,%3};"
        : "+f"(c[0]), "+f"(c[1]), "+f"(c[2]), "+f"(c[3])
        : "r"(a[0]), "r"(a[1]), "r"(a[2]), "r"(a[3]), "r"(b[0]), "r"(b[1]));
}

DEV void ldsm4(unsigned& r0, unsigned& r1, unsigned& r2, unsigned& r3, unsigned a) {
    asm volatile("ldmatrix.sync.aligned.m8n8.x4.shared.b16 {%0,%1,%2,%3}, [%4];"
        : "=r"(r0), "=r"(r1), "=r"(r2), "=r"(r3) : "r"(a));
}

DEV unsigned sa(const void* p) { return (unsigned)__cvta_generic_to_shared(p); }

// Lane mapping shared by all LDSM tiles:
//  rowsel = lane&7, tsel = lane>>3
//  tile t: kp offset = (t&1)*4, row offset = (t>>1)*8
//  => r0=(row, kb), r1=(row, kb+4), r2=(row+8, kb), r3=(row+8, kb+4)
//  A frag (a0,a1,a2,a3) = (r0, r2, r1, r3);  B frags: {r0,r1}, {r2,r3}

// ---------------------------------------------------------------------------
// LayerNorm over C=96, with optional (+shift,+shift) gather (implements roll)
// ---------------------------------------------------------------------------
__global__ void ln_kernel(const float* __restrict__ in, const float* __restrict__ g,
                          const float* __restrict__ bt, float* __restrict__ out, int shift)
{
    int gid  = blockIdx.x * blockDim.x + threadIdx.x;
    int tok  = gid >> 5;
    int lane = gid & 31;
    if (tok >= TOK) return;
    int b = tok >> 16, rr = tok & 65535, h = rr >> 8, w = rr & 255;
    const float* src = in + (size_t)((b << 16) | (((h + shift) & 255) << 8) | ((w + shift) & 255)) * 96;
    float v0 = src[lane], v1 = src[lane + 32], v2 = src[lane + 64];
    float s = v0 + v1 + v2;
    #pragma unroll
    for (int o = 16; o > 0; o >>= 1) s += __shfl_xor_sync(0xffffffffu, s, o);
    float mu = s * (1.0f / 96.0f);
    float d0 = v0 - mu, d1 = v1 - mu, d2 = v2 - mu;
    float sq = d0 * d0 + d1 * d1 + d2 * d2;
    #pragma unroll
    for (int o = 16; o > 0; o >>= 1) sq += __shfl_xor_sync(0xffffffffu, sq, o);
    float inv = rsqrtf(sq * (1.0f / 96.0f) + 1e-5f);
    float* dst = out + (size_t)tok * 96;
    dst[lane]      = d0 * inv * g[lane]      + bt[lane];
    dst[lane + 32] = d1 * inv * g[lane + 32] + bt[lane + 32];
    dst[lane + 64] = d2 * inv * g[lane + 64] + bt[lane + 64];
}

// ---------------------------------------------------------------------------
// Tensor-core GEMM (fp16 m16n8k16 + ldmatrix).
// W is the ORIGINAL [out][K] weight (k-contiguous => col-major B frags).
// Block: 128 rows x 96 cols, 8 warps (4 Mquad x 2 Nhalf); warp 2x6 frags.
// Smem (u32 k-pairs): As[128][AP], Ws[96][AP], AP = K/2+4.
// MODE 0 plain (outN cols), 1 proj: roll(+4,+4)+residual, 2 residual.
// ACT 0 none, 1 gelu.
// ---------------------------------------------------------------------------
template<int K, int ACT, int MODE>
__global__ void __launch_bounds__(256) gemm_h(
        const float* __restrict__ A, const float* __restrict__ W,
        const float* __restrict__ bias, const float* __restrict__ res,
        float* __restrict__ out, int n0_off, int outN)
{
    constexpr int KP = K / 2;
    constexpr int AP = KP + 4;                  // 52 (%32=20) or 100 (%32=4)
    extern __shared__ unsigned smem_u[];
    unsigned* As = smem_u;                      // 128*AP
    unsigned* Ws = smem_u + 128 * AP;           // 96*AP
    int m0 = blockIdx.x * 128;
    int n0 = (blockIdx.y + n0_off) * 96;
    int t  = threadIdx.x;
    int warp = t >> 5, lane = t & 31;
    int wm = warp >> 1, wn = warp & 1;
    int g = lane >> 2, tg = lane & 3;

    #pragma unroll
    for (int i = 0; i < 128 * KP / 256; i++) {
        int idx = t + i * 256;
        int m = idx / KP, kp = idx % KP;
        float2 v = *reinterpret_cast<const float2*>(A + (size_t)(m0 + m) * K + 2 * kp);
        As[m * AP + kp] = packh2(v.x, v.y);
    }
    #pragma unroll
    for (int i = 0; i < 96 * KP / 256; i++) {
        int idx = t + i * 256;
        int c = idx / KP, kp = idx % KP;
        float2 v = *reinterpret_cast<const float2*>(W + (size_t)(n0 + c) * K + 2 * kp);
        Ws[c * AP + kp] = packh2(v.x, v.y);
    }
    __syncthreads();

    int rowsel = lane & 7, tsel = lane >> 3;
    int kpoff  = (tsel & 1) * 4, rowoff = (tsel >> 1) * 8;

    unsigned aaddr[2], baddr[3];
    #pragma unroll
    for (int i = 0; i < 2; i++)
        aaddr[i] = sa(&As[((wm * 2 + i) * 16 + rowsel + rowoff) * AP + kpoff]);
    #pragma unroll
    for (int jj = 0; jj < 3; jj++)
        baddr[jj] = sa(&Ws[(wn * 48 + jj * 16 + rowsel + rowoff) * AP + kpoff]);

    float acc[2][6][4];
    #pragma unroll
    for (int i = 0; i < 2; i++)
        #pragma unroll
        for (int j = 0; j < 6; j++)
            #pragma unroll
            for (int q = 0; q < 4; q++) acc[i][j][q] = 0.0f;

    #pragma unroll
    for (int s = 0; s < K / 16; s++) {
        unsigned off = s * 32;                 // 8 u32 = 32 bytes
        unsigned a[2][4];
        #pragma unroll
        for (int i = 0; i < 2; i++) {
            unsigned r0, r1, r2, r3;
            ldsm4(r0, r1, r2, r3, aaddr[i] + off);
            a[i][0] = r0; a[i][1] = r2; a[i][2] = r1; a[i][3] = r3;
        }
        #pragma unroll
        for (int jj = 0; jj < 3; jj++) {
            unsigned r0, r1, r2, r3;
            ldsm4(r0, r1, r2, r3, baddr[jj] + off);
            unsigned b0[2] = {r0, r1}, b1[2] = {r2, r3};
            #pragma unroll
            for (int i = 0; i < 2; i++) {
                mma_f16(acc[i][2 * jj],     a[i], b0);
                mma_f16(acc[i][2 * jj + 1], a[i], b1);
            }
        }
    }

    #pragma unroll
    for (int i = 0; i < 2; i++) {
        int rb = m0 + (wm * 2 + i) * 16;
        #pragma unroll
        for (int j = 0; j < 6; j++) {
            int c = n0 + wn * 48 + j * 8 + tg * 2;
            #pragma unroll
            for (int half = 0; half < 2; half++) {
                int row = rb + g + half * 8;
                float v0 = acc[i][j][half * 2]     + bias[c];
                float v1 = acc[i][j][half * 2 + 1] + bias[c + 1];
                if (ACT == 1) { v0 = gelu_f(v0); v1 = gelu_f(v1); }
                if (MODE == 0) {
                    out[(size_t)row * outN + c]     = v0;
                    out[(size_t)row * outN + c + 1] = v1;
                } else if (MODE == 1) {
                    int bb = row >> 16, rr = row & 65535, hy = rr >> 8, wx = rr & 255;
                    int tr = (bb << 16) | (((hy + 4) & 255) << 8) | ((wx + 4) & 255);
                    out[(size_t)tr * 96 + c]     = res[(size_t)tr * 96 + c]     + v0;
                    out[(size_t)tr * 96 + c + 1] = res[(size_t)tr * 96 + c + 1] + v1;
                } else {
                    out[(size_t)row * 96 + c]     = res[(size_t)row * 96 + c]     + v0;
                    out[(size_t)row * 96 + c + 1] = res[(size_t)row * 96 + c + 1] + v1;
                }
            }
        }
    }
}

// ---------------------------------------------------------------------------
// Tensor-core 3x3 SAME conv (implicit GEMM, fp16 m16n8k16 + ldmatrix), NHWC.
// Block: 16x16 pixel tile x 96 outputs; halo 18x18 pixel-major in smem
// [324 pos][20 kpair]; channel chunk KC=32 (2 k16-steps per tap).
// Warp: 4 m-frags x 6 n-frags. grid.z = b*(COUT/96) + cohalf.
// ACT: 0 none,1 relu,2 gelu. RES: residual.
// ---------------------------------------------------------------------------
template<int CIN, int COUT, int ACT, int RES>
__global__ void __launch_bounds__(256) conv_h(
        const float* __restrict__ in, const float* __restrict__ w,
        const float* __restrict__ bias, const float* __restrict__ res,
        float* __restrict__ out)
{
    constexpr int KC = 32;            // input channels per chunk (16 kpairs)
    constexpr int PIT = 20;           // kpair pitch (%32=20, 16B-mult)
    constexpr int NH = COUT / 96;
    extern __shared__ unsigned smem_u[];
    unsigned* ws_u  = smem_u;                       // [9][96][PIT]
    unsigned* ins_u = smem_u + 9 * 96 * PIT;        // [324][PIT]

    int x0 = blockIdx.x * 16, y0 = blockIdx.y * 16;
    int zb = blockIdx.z;
    int cohalf = (NH == 1) ? 0 : (zb & 1);
    int b      = (NH == 1) ? zb : (zb >> 1);
    int t  = threadIdx.x;
    int warp = t >> 5, lane = t & 31;
    int wm = warp >> 1, wn = warp & 1;
    int g = lane >> 2, tg = lane & 3;

    int rowsel = lane & 7, tsel = lane >> 3;
    int kpoff  = (tsel & 1) * 4, rowoff = (tsel >> 1) * 8;

    // per-thread LDSM base addresses
    unsigned abase = sa(ins_u) + ((rowsel + rowoff) * PIT + kpoff) * 4;
    unsigned bbase[3];
    #pragma unroll
    for (int jj = 0; jj < 3; jj++)
        bbase[jj] = sa(&ws_u[(wn * 48 + jj * 16 + rowsel + rowoff) * PIT + kpoff]);

    float acc[4][6][4];
    #pragma unroll
    for (int i = 0; i < 4; i++)
        #pragma unroll
        for (int j = 0; j < 6; j++)
            #pragma unroll
            for (int q = 0; q < 4; q++) acc[i][j][q] = 0.0f;

    for (int ci0 = 0; ci0 < CIN; ci0 += KC) {
        // stage halo 18x18 x KC, pixel-major [pos][kpair]
        for (int idx = t; idx < 324 * 16; idx += 256) {
            int cip = idx & 15, pos = idx >> 4;
            int hp = pos / 18, wp = pos % 18;
            int gy = y0 + hp - 1, gx = x0 + wp - 1;
            unsigned pv = 0;
            if ((unsigned)gy < 256u && (unsigned)gx < 256u) {
                float2 v = *reinterpret_cast<const float2*>(
                    in + (size_t)((b << 16) | (gy << 8) | gx) * CIN + ci0 + 2 * cip);
                pv = packh2(v.x, v.y);
            }
            ins_u[pos * PIT + cip] = pv;
        }
        // stage weights 9 x KC x 96 (this cohalf), [tap][co][kpair]
        for (int idx = t; idx < 9 * 16 * 96; idx += 256) {
            int co = idx % 96;
            int r2 = idx / 96;
            int cip = r2 % 16, tap = r2 / 16;
            size_t base = ((size_t)(tap * CIN + ci0 + 2 * cip)) * COUT + cohalf * 96 + co;
            ws_u[(tap * 96 + co) * PIT + cip] = packh2(w[base], w[base + COUT]);
        }
        __syncthreads();

        #pragma unroll
        for (int dy = 0; dy < 3; dy++) {
            #pragma unroll
            for (int dx = 0; dx < 3; dx++) {
                unsigned woff = (unsigned)((dy * 3 + dx) * 96 * PIT) * 4;
                #pragma unroll
                for (int s = 0; s < 2; s++) {
                    unsigned soff = s * 32;
                    unsigned a[4][4];
                    #pragma unroll
                    for (int i = 0; i < 4; i++) {
                        int pos = (wm * 4 + i + dy) * 18 + dx;
                        unsigned r0, r1, r2, r3;
                        ldsm4(r0, r1, r2, r3, abase + (unsigned)(pos * PIT) * 4 + soff);
                        a[i][0] = r0; a[i][1] = r2; a[i][2] = r1; a[i][3] = r3;
                    }
                    #pragma unroll
                    for (int jj = 0; jj < 3; jj++) {
                        unsigned r0, r1, r2, r3;
                        ldsm4(r0, r1, r2, r3, bbase[jj] + woff + soff);
                        unsigned b0[2] = {r0, r1}, b1[2] = {r2, r3};
                        #pragma unroll
                        for (int i = 0; i < 4; i++) {
                            mma_f16(acc[i][2 * jj],     a[i], b0);
                            mma_f16(acc[i][2 * jj + 1], a[i], b1);
                        }
                    }
                }
            }
        }
        __syncthreads();
    }

    #pragma unroll
    for (int i = 0; i < 4; i++) {
        int y = y0 + wm * 4 + i;
        #pragma unroll
        for (int j = 0; j < 6; j++) {
            int co = cohalf * 96 + wn * 48 + j * 8 + tg * 2;
            float b0 = bias[co], b1 = bias[co + 1];
            #pragma unroll
            for (int half = 0; half < 2; half++) {
                int x = x0 + g + half * 8;
                size_t base = (size_t)((b << 16) | (y << 8) | x) * COUT + co;
                float v0 = acc[i][j][half * 2]     + b0;
                float v1 = acc[i][j][half * 2 + 1] + b1;
                if (ACT == 1) { v0 = fmaxf(v0, 0.0f); v1 = fmaxf(v1, 0.0f); }
                if (ACT == 2) { v0 = gelu_f(v0); v1 = gelu_f(v1); }
                if (RES) { v0 += res[base]; v1 += res[base + 1]; }
                out[base]     = v0;
                out[base + 1] = v1;
            }
        }
    }
}

// ---------------------------------------------------------------------------
// Windowed dual attention. One block per (window, head). 64 threads = rows.
// ---------------------------------------------------------------------------
DEV int regio(int wblk, int i) { return (wblk < 31) ? 0 : ((i < 4) ? 1 : 2); }

DEV void attn_pass(const float4 (*K4)[4], const float4 (*V4)[4], const float4 q[4],
                   float lsv, const float* rpb_s, int i1, int j1, int cnt1,
                   int wh, int ww, float4 o[4])
{
    float s[64];
    #pragma unroll
    for (int m = 0; m < 64; m++) {
        const float4* kr = K4[m];
        float d;
        d  = q[0].x * kr[0].x + q[0].y * kr[0].y + q[0].z * kr[0].z + q[0].w * kr[0].w;
        d += q[1].x * kr[1].x + q[1].y * kr[1].y + q[1].z * kr[1].z + q[1].w * kr[1].w;
        d += q[2].x * kr[2].x + q[2].y * kr[2].y + q[2].z * kr[2].z + q[2].w * kr[2].w;
        d += q[3].x * kr[3].x + q[3].y * kr[3].y + q[3].z * kr[3].z + q[3].w * kr[3].w;
        int i2 = m >> 3, j2 = m & 7;
        float rb = rpb_s[(i1 - i2 + 7) * 15 + (j1 - j2 + 7)];
        int cnt2 = regio(wh, i2) * 3 + regio(ww, j2);
        s[m] = d * lsv + rb + ((cnt1 != cnt2) ? -100.0f : 0.0f);
    }
    float mx = s[0];
    #pragma unroll
    for (int m = 1; m < 64; m++) mx = fmaxf(mx, s[m]);
    float sum = 0.0f;
    float4 a0 = make_float4(0, 0, 0, 0), a1 = a0, a2 = a0, a3 = a0;
    #pragma unroll
    for (int m = 0; m < 64; m++) {
        float p = expf(s[m] - mx);
        sum += p;
        const float4* vr = V4[m];
        a0.x += p * vr[0].x; a0.y += p * vr[0].y; a0.z += p * vr[0].z; a0.w += p * vr[0].w;
        a1.x += p * vr[1].x; a1.y += p * vr[1].y; a1.z += p * vr[1].z; a1.w += p * vr[1].w;
        a2.x += p * vr[2].x; a2.y += p * vr[2].y; a2.z += p * vr[2].z; a2.w += p * vr[2].w;
        a3.x += p * vr[3].x; a3.y += p * vr[3].y; a3.z += p * vr[3].z; a3.w += p * vr[3].w;
    }
    float inv = 1.0f / sum;
    o[0] = make_float4(a0.x * inv, a0.y * inv, a0.z * inv, a0.w * inv);
    o[1] = make_float4(a1.x * inv, a1.y * inv, a1.z * inv, a1.w * inv);
    o[2] = make_float4(a2.x * inv, a2.y * inv, a2.z * inv, a2.w * inv);
    o[3] = make_float4(a3.x * inv, a3.y * inv, a3.z * inv, a3.w * inv);
}

__global__ void attn_kernel(const float* __restrict__ qkvx, const float* __restrict__ qkvr,
                            const float* __restrict__ lsp, const float* __restrict__ gat,
                            const float* __restrict__ rpbt, float* __restrict__ out)
{
    __shared__ float4 ks[64][4], vs[64][4], krs[64][4], vrs[64][4];
    __shared__ float rpb_s[225];
    int blk  = blockIdx.x;
    int head = blk % HEADS;
    int widx = blk / HEADS;
    int b  = widx >> 10;
    int nw = widx & 1023;
    int wh = nw >> 5, ww = nw & 31;
    int n  = threadIdx.x;
    int i1 = n >> 3, j1 = n & 7;

    size_t tok = (size_t)((b << 16) | ((wh * 8 + i1) << 8) | (ww * 8 + j1));
    size_t rowbase = tok * 288 + head * 16;

    float4 q[4];
    {
        const float4* qp = (const float4*)(qkvx + rowbase);
        q[0] = qp[0]; q[1] = qp[1]; q[2] = qp[2]; q[3] = qp[3];
        float ss = 0.0f;
        #pragma unroll
        for (int i = 0; i < 4; i++)
            ss += q[i].x * q[i].x + q[i].y * q[i].y + q[i].z * q[i].z + q[i].w * q[i].w;
        float inv = 1.0f / fmaxf(sqrtf(ss), 1e-12f);
        #pragma unroll
        for (int i = 0; i < 4; i++) { q[i].x *= inv; q[i].y *= inv; q[i].z *= inv; q[i].w *= inv; }
    }
    {
        const float4* kp = (const float4*)(qkvx + rowbase + 96);
        float4 kv[4] = {kp[0], kp[1], kp[2], kp[3]};
        float ss = 0.0f;
        #pragma unroll
        for (int i = 0; i < 4; i++)
            ss += kv[i].x * kv[i].x + kv[i].y * kv[i].y + kv[i].z * kv[i].z + kv[i].w * kv[i].w;
        float inv = 1.0f / fmaxf(sqrtf(ss), 1e-12f);
        #pragma unroll
        for (int i = 0; i < 4; i++)
            ks[n][i] = make_float4(kv[i].x * inv, kv[i].y * inv, kv[i].z * inv, kv[i].w * inv);
        const float4* vp = (const float4*)(qkvx + rowbase + 192);
        #pragma unroll
        for (int i = 0; i < 4; i++) vs[n][i] = vp[i];
    }
    {
        const float4* kp = (const float4*)(qkvr + rowbase + 96);
        float4 kv[4] = {kp[0], kp[1], kp[2], kp[3]};
        float ss = 0.0f;
        #pragma unroll
        for (int i = 0; i < 4; i++)
            ss += kv[i].x * kv[i].x + kv[i].y * kv[i].y + kv[i].z * kv[i].z + kv[i].w * kv[i].w;
        float inv = 1.0f / fmaxf(sqrtf(ss), 1e-12f);
        #pragma unroll
        for (int i = 0; i < 4; i++)
            krs[n][i] = make_float4(kv[i].x * inv, kv[i].y * inv, kv[i].z * inv, kv[i].w * inv);
        const float4* vp = (const float4*)(qkvr + rowbase + 192);
        #pragma unroll
        for (int i = 0; i < 4; i++) vrs[n][i] = vp[i];
    }
    for (int idx = n; idx < 225; idx += 64) rpb_s[idx] = rpbt[idx * 6 + head];

    float lsv = expf(fminf(lsp[head], 4.605170185988092f));
    float gv  = 1.0f / (1.0f + expf(-gat[head]));
    int cnt1 = regio(wh, i1) * 3 + regio(ww, j1);
    __syncthreads();

    float4 o1[4], o2[4];
    attn_pass(ks,  vs,  q, lsv, rpb_s, i1, j1, cnt1, wh, ww, o1);
    attn_pass(krs, vrs, q, lsv, rpb_s, i1, j1, cnt1, wh, ww, o2);

    float4* op = (float4*)(out + tok * 96 + head * 16);
    float og = 1.0f - gv;
    #pragma unroll
    for (int i = 0; i < 4; i++)
        op[i] = make_float4(og * o1[i].x + gv * o2[i].x,
                            og * o1[i].y + gv * o2[i].y,
                            og * o1[i].z + gv * o2[i].z,
                            og * o1[i].w + gv * o2[i].w);
}

// ---------------------------------------------------------------------------
// Host orchestration
// ---------------------------------------------------------------------------
static int g_attr_done = 0;

extern "C" void kernel_launch(void* const* d_in, const int* in_sizes, int n_in,
                              void* d_out, int out_size)
{
    const float* x       = (const float*)d_in[0];
    const float* ref     = (const float*)d_in[1];
    const float* n1g     = (const float*)d_in[2];
    const float* n1b     = (const float*)d_in[3];
    const float* qkv_w   = (const float*)d_in[4];
    const float* qkv_b   = (const float*)d_in[5];
    const float* lscale  = (const float*)d_in[6];
    const float* gating  = (const float*)d_in[7];
    const float* rpbt    = (const float*)d_in[8];
    const float* trunk_w = (const float*)d_in[9];
    const float* trunk_b = (const float*)d_in[10];
    const float* proj_w  = (const float*)d_in[11];
    const float* proj_b  = (const float*)d_in[12];
    const float* n2g     = (const float*)d_in[13];
    const float* n2b     = (const float*)d_in[14];
    const float* fc1_w   = (const float*)d_in[15];
    const float* fc1_b   = (const float*)d_in[16];
    const float* convm_w = (const float*)d_in[17];
    const float* convm_b = (const float*)d_in[18];
    const float* fc2_w   = (const float*)d_in[19];
    const float* fc2_b   = (const float*)d_in[20];
    float* out = (float*)d_out;

    float *lnx, *lnr, *qkvx, *qkvr, *ybuf, *tmp, *x2, *h1, *h2;
    cudaGetSymbolAddress((void**)&lnx,  g_lnx);
    cudaGetSymbolAddress((void**)&lnr,  g_lnr);
    cudaGetSymbolAddress((void**)&qkvx, g_qkvx);
    cudaGetSymbolAddress((void**)&qkvr, g_qkvr);
    cudaGetSymbolAddress((void**)&ybuf, g_y);
    cudaGetSymbolAddress((void**)&tmp,  g_tmp);
    cudaGetSymbolAddress((void**)&x2,   g_x2);
    cudaGetSymbolAddress((void**)&h1,   g_h1);
    cudaGetSymbolAddress((void**)&h2,   g_h2);

    const int CONV_SMEM    = (9 * 96 * 20 + 324 * 20) * 4;   // 95040
    const int GEMM_SMEM96  = (128 * 52 + 96 * 52) * 4;       // 46592
    const int GEMM_SMEM192 = (128 * 100 + 96 * 100) * 4;     // 89600

    if (!g_attr_done) {
        cudaFuncSetAttribute(conv_h<96, 96, 1, 0>,   cudaFuncAttributeMaxDynamicSharedMemorySize, CONV_SMEM);
        cudaFuncSetAttribute(conv_h<96, 96, 0, 1>,   cudaFuncAttributeMaxDynamicSharedMemorySize, CONV_SMEM);
        cudaFuncSetAttribute(conv_h<192, 192, 2, 0>, cudaFuncAttributeMaxDynamicSharedMemorySize, CONV_SMEM);
        cudaFuncSetAttribute(gemm_h<96, 0, 0>,  cudaFuncAttributeMaxDynamicSharedMemorySize, GEMM_SMEM96);
        cudaFuncSetAttribute(gemm_h<96, 1, 0>,  cudaFuncAttributeMaxDynamicSharedMemorySize, GEMM_SMEM96);
        cudaFuncSetAttribute(gemm_h<96, 0, 1>,  cudaFuncAttributeMaxDynamicSharedMemorySize, GEMM_SMEM96);
        cudaFuncSetAttribute(gemm_h<192, 0, 2>, cudaFuncAttributeMaxDynamicSharedMemorySize, GEMM_SMEM192);
        g_attr_done = 1;
    }

    ln_kernel<<<TOK / 8, 256>>>(x,   n1g, n1b, lnx, 4);
    ln_kernel<<<TOK / 8, 256>>>(ref, n1g, n1b, lnr, 4);

    gemm_h<96, 0, 0><<<dim3(TOK / 128, 3), 256, GEMM_SMEM96>>>(lnx, qkv_w, qkv_b, nullptr, qkvx, 0, 288);
    gemm_h<96, 0, 0><<<dim3(TOK / 128, 2), 256, GEMM_SMEM96>>>(lnr, qkv_w, qkv_b, nullptr, qkvr, 1, 288);

    attn_kernel<<<Bb * 1024 * HEADS, 64>>>(qkvx, qkvr, lscale, gating, rpbt, ybuf);

    conv_h<96, 96, 1, 0><<<dim3(16, 16, Bb), 256, CONV_SMEM>>>(ybuf, trunk_w,             trunk_b,       nullptr, tmp);
    conv_h<96, 96, 0, 1><<<dim3(16, 16, Bb), 256, CONV_SMEM>>>(tmp,  trunk_w + 1 * 82944, trunk_b + 96,  ybuf,    ybuf);
    conv_h<96, 96, 1, 0><<<dim3(16, 16, Bb), 256, CONV_SMEM>>>(ybuf, trunk_w + 2 * 82944, trunk_b + 192, nullptr, tmp);
    conv_h<96, 96, 0, 1><<<dim3(16, 16, Bb), 256, CONV_SMEM>>>(tmp,  trunk_w + 3 * 82944, trunk_b + 288, ybuf,    ybuf);

    gemm_h<96, 0, 1><<<dim3(TOK / 128, 1), 256, GEMM_SMEM96>>>(ybuf, proj_w, proj_b, x, x2, 0, 96);

    ln_kernel<<<TOK / 8, 256>>>(x2, n2g, n2b, tmp, 0);
    gemm_h<96, 1, 0><<<dim3(TOK / 128, 2), 256, GEMM_SMEM96>>>(tmp, fc1_w, fc1_b, nullptr, h1, 0, 192);
    conv_h<192, 192, 2, 0><<<dim3(16, 16, Bb * 2), 256, CONV_SMEM>>>(h1, convm_w, convm_b, nullptr, h2);
    gemm_h<192, 0, 2><<<dim3(TOK / 128, 1), 256, GEMM_SMEM192>>>(h2, fc2_w, fc2_b, x2, out, 0, 96);
}

// round 7
// speedup vs baseline: 1.5852x; 1.5852x over previous
#include <cuda_runtime.h>
#include <cuda_fp16.h>
#include <math.h>

// ---------------------------------------------------------------------------
// Problem constants
// ---------------------------------------------------------------------------
constexpr int Bb   = 2;
constexpr int Cc   = 96;
constexpr int HEADS= 6;
constexpr int TOK  = Bb * 256 * 256;          // 131072 tokens

// ---------------------------------------------------------------------------
// Static device scratch
// ---------------------------------------------------------------------------
__device__ float g_qkvx[TOK * 288];
__device__ float g_qkvr[TOK * 288];
__device__ float g_y   [TOK * Cc];            // fp32 (residual carrier)
__device__ float g_x2  [TOK * Cc];

__device__ __half g_ln16 [TOK * 96];
__device__ __half g_lnr16[TOK * 96];
__device__ __half g_y16  [TOK * 96];
__device__ __half g_t16  [TOK * 96];
__device__ __half g_h16  [TOK * 192];
__device__ __half g_h16b [TOK * 192];

__device__ __half g_qkvw16[288 * 96];
__device__ __half g_projw16[96 * 96];
__device__ __half g_fc1w16[192 * 96];
__device__ __half g_fc2w16[96 * 192];
__device__ __half g_trunkw16[36 * 96 * 96];   // [layer*9+tap][co][ci]
__device__ __half g_convmw16[9 * 192 * 192];  // [tap][co][ci]

#define DEV __device__ __forceinline__

DEV float gelu_f(float v) { return 0.5f * v * (1.0f + erff(v * 0.70710678118654752f)); }

// D += A(16x16, f16, row) * B(16x8, f16, col), fp32 accum
DEV void mma_f16(float* c, const unsigned* a, const unsigned* b) {
    asm("mma.sync.aligned.m16n8k16.row.col.f32.f16.f16.f32 "
        "{%0,%1,%2,%3}, {%4,%5,%6,%7}, {%8,%9}, {%0,%1,%2,%3};"
        : "+f"(c[0]), "+f"(c[1]), "+f"(c[2]), "+f"(c[3])
        : "r"(a[0]), "r"(a[1]), "r"(a[2]), "r"(a[3]), "r"(b[0]), "r"(b[1]));
}

DEV unsigned sa(const void* p) { return (unsigned)__cvta_generic_to_shared(p); }

DEV void cpa16(unsigned dst, const void* src) {
    asm volatile("cp.async.cg.shared.global [%0], [%1], 16;"
                 :: "r"(dst), "l"(__cvta_generic_to_global(src)));
}
DEV void cpa_commit_wait() {
    asm volatile("cp.async.commit_group;");
    asm volatile("cp.async.wait_group 0;" ::: "memory");
}

// ---------------------------------------------------------------------------
// Weight conversion: fp32 -> fp16, same layout
// ---------------------------------------------------------------------------
__global__ void tohalf_k(const float* __restrict__ src, __half* __restrict__ dst, int n)
{
    int i = blockIdx.x * 256 + threadIdx.x;
    if (i < n) dst[i] = __float2half_rn(src[i]);
}

// fp32 [tap][ci][co] -> fp16 [tap][co][ci]
__global__ void tohalfT_k(const float* __restrict__ src, __half* __restrict__ dst,
                          int CI, int CO, int ntap)
{
    int i = blockIdx.x * 256 + threadIdx.x;
    if (i >= ntap * CI * CO) return;
    int ci = i % CI, co = (i / CI) % CO, tap = i / (CI * CO);
    dst[i] = __float2half_rn(src[((size_t)tap * CI + ci) * CO + co]);
}

// ---------------------------------------------------------------------------
// LayerNorm over C=96, optional (+shift,+shift) gather; fp16 output
// ---------------------------------------------------------------------------
__global__ void ln_kernel(const float* __restrict__ in, const float* __restrict__ g,
                          const float* __restrict__ bt, __half* __restrict__ out, int shift)
{
    int gid  = blockIdx.x * blockDim.x + threadIdx.x;
    int tok  = gid >> 5;
    int lane = gid & 31;
    if (tok >= TOK) return;
    int b = tok >> 16, rr = tok & 65535, h = rr >> 8, w = rr & 255;
    const float* src = in + (size_t)((b << 16) | (((h + shift) & 255) << 8) | ((w + shift) & 255)) * 96;
    float v0 = src[lane], v1 = src[lane + 32], v2 = src[lane + 64];
    float s = v0 + v1 + v2;
    #pragma unroll
    for (int o = 16; o > 0; o >>= 1) s += __shfl_xor_sync(0xffffffffu, s, o);
    float mu = s * (1.0f / 96.0f);
    float d0 = v0 - mu, d1 = v1 - mu, d2 = v2 - mu;
    float sq = d0 * d0 + d1 * d1 + d2 * d2;
    #pragma unroll
    for (int o = 16; o > 0; o >>= 1) sq += __shfl_xor_sync(0xffffffffu, sq, o);
    float inv = rsqrtf(sq * (1.0f / 96.0f) + 1e-5f);
    __half* dst = out + (size_t)tok * 96;
    dst[lane]      = __float2half_rn(d0 * inv * g[lane]      + bt[lane]);
    dst[lane + 32] = __float2half_rn(d1 * inv * g[lane + 32] + bt[lane + 32]);
    dst[lane + 64] = __float2half_rn(d2 * inv * g[lane + 64] + bt[lane + 64]);
}

// ---------------------------------------------------------------------------
// Tensor-core GEMM (fp16 m16n8k16), cp.async staging from fp16 mirrors.
// Block: 128 rows x 96 cols, 8 warps (4 Mquad x 2 Nhalf); warp 2x6 frags.
// Smem (u32 kpairs): As[128][AP], Ws[96][AP], AP = K/2+4.
// MODE 0 fp32 plain, 1 proj roll+res fp32, 2 res fp32, 3 fp16 plain.
// ACT 0 none, 1 gelu.
// ---------------------------------------------------------------------------
template<int K, int ACT, int MODE>
__global__ void __launch_bounds__(256) gemm_h(
        const __half* __restrict__ A, const __half* __restrict__ W,
        const float* __restrict__ bias, const float* __restrict__ res,
        float* __restrict__ out, __half* __restrict__ out16, int n0_off, int outN)
{
    constexpr int KP = K / 2;
    constexpr int AP = KP + 4;                  // 52 or 100 (%32 = 20 / 4)
    constexpr int CH = K / 8;                   // 16B chunks per row
    extern __shared__ unsigned smem_u[];
    unsigned* As = smem_u;                      // 128*AP
    unsigned* Ws = smem_u + 128 * AP;           // 96*AP
    int m0 = blockIdx.x * 128;
    int n0 = (blockIdx.y + n0_off) * 96;
    int t  = threadIdx.x;
    int warp = t >> 5, lane = t & 31;
    int wm = warp >> 1, wn = warp & 1;
    int g = lane >> 2, tg = lane & 3;

    unsigned as_base = sa(As), ws_base = sa(Ws);
    #pragma unroll
    for (int i = 0; i < 128 * CH / 256; i++) {
        int idx = t + i * 256;
        int m = idx / CH, c = idx % CH;
        cpa16(as_base + (unsigned)(m * AP + c * 4) * 4, A + (size_t)(m0 + m) * K + c * 8);
    }
    for (int idx = t; idx < 96 * CH; idx += 256) {
        int c = idx / CH, ck = idx % CH;
        cpa16(ws_base + (unsigned)(c * AP + ck * 4) * 4, W + (size_t)(n0 + c) * K + ck * 8);
    }
    cpa_commit_wait();
    __syncthreads();

    float acc[2][6][4];
    #pragma unroll
    for (int i = 0; i < 2; i++)
        #pragma unroll
        for (int j = 0; j < 6; j++)
            #pragma unroll
            for (int q = 0; q < 4; q++) acc[i][j][q] = 0.0f;

    #pragma unroll
    for (int s = 0; s < K / 16; s++) {
        int kb = s * 8;
        unsigned a[2][4];
        #pragma unroll
        for (int i = 0; i < 2; i++) {
            int mb = (wm * 2 + i) * 16;
            a[i][0] = As[(mb + g)     * AP + kb + tg];
            a[i][1] = As[(mb + g + 8) * AP + kb + tg];
            a[i][2] = As[(mb + g)     * AP + kb + tg + 4];
            a[i][3] = As[(mb + g + 8) * AP + kb + tg + 4];
        }
        unsigned b[6][2];
        #pragma unroll
        for (int j = 0; j < 6; j++) {
            int col = wn * 48 + j * 8 + g;
            b[j][0] = Ws[col * AP + kb + tg];
            b[j][1] = Ws[col * AP + kb + tg + 4];
        }
        #pragma unroll
        for (int i = 0; i < 2; i++)
            #pragma unroll
            for (int j = 0; j < 6; j++) mma_f16(acc[i][j], a[i], b[j]);
    }

    #pragma unroll
    for (int i = 0; i < 2; i++) {
        int rb = m0 + (wm * 2 + i) * 16;
        #pragma unroll
        for (int j = 0; j < 6; j++) {
            int c = n0 + wn * 48 + j * 8 + tg * 2;
            #pragma unroll
            for (int half = 0; half < 2; half++) {
                int row = rb + g + half * 8;
                float v0 = acc[i][j][half * 2]     + bias[c];
                float v1 = acc[i][j][half * 2 + 1] + bias[c + 1];
                if (ACT == 1) { v0 = gelu_f(v0); v1 = gelu_f(v1); }
                if (MODE == 0) {
                    out[(size_t)row * outN + c]     = v0;
                    out[(size_t)row * outN + c + 1] = v1;
                } else if (MODE == 1) {
                    int bb = row >> 16, rr = row & 65535, hy = rr >> 8, wx = rr & 255;
                    int tr = (bb << 16) | (((hy + 4) & 255) << 8) | ((wx + 4) & 255);
                    out[(size_t)tr * 96 + c]     = res[(size_t)tr * 96 + c]     + v0;
                    out[(size_t)tr * 96 + c + 1] = res[(size_t)tr * 96 + c + 1] + v1;
                } else if (MODE == 2) {
                    out[(size_t)row * 96 + c]     = res[(size_t)row * 96 + c]     + v0;
                    out[(size_t)row * 96 + c + 1] = res[(size_t)row * 96 + c + 1] + v1;
                } else {
                    *(__half2*)&out16[(size_t)row * outN + c] =
                        __floats2half2_rn(v0, v1);
                }
            }
        }
    }
}

// ---------------------------------------------------------------------------
// Tensor-core 3x3 SAME conv (implicit GEMM, fp16 m16n8k16), cp.async staging.
// in16: NHWC fp16 mirror. w16t: [tap][co][ci] fp16. Halo smem [324][20].
// Block: 16x16 px x 96 cout; KC=32 ci per chunk; warp 4x6 frags.
// grid.z = b*(COUT/96)+cohalf. ACT 0/1/2 = none/relu/gelu.
// ---------------------------------------------------------------------------
template<int CIN, int COUT, int ACT, int RES, int O32, int O16>
__global__ void __launch_bounds__(256) conv_h(
        const __half* __restrict__ in16, const __half* __restrict__ w16t,
        const float* __restrict__ bias, const float* __restrict__ res,
        float* __restrict__ out32, __half* __restrict__ out16)
{
    constexpr int PIT = 20;           // kpair pitch (u32), %32 = 20
    constexpr int NH = COUT / 96;
    extern __shared__ unsigned smem_u[];
    unsigned* ws_u  = smem_u;                       // [9*96][PIT]
    unsigned* ins_u = smem_u + 9 * 96 * PIT;        // [324][PIT]

    int x0 = blockIdx.x * 16, y0 = blockIdx.y * 16;
    int zb = blockIdx.z;
    int cohalf = (NH == 1) ? 0 : (zb & 1);
    int b      = (NH == 1) ? zb : (zb >> 1);
    int t  = threadIdx.x;
    int warp = t >> 5, lane = t & 31;
    int wm = warp >> 1, wn = warp & 1;
    int g = lane >> 2, tg = lane & 3;

    unsigned ins_base = sa(ins_u), ws_base = sa(ws_u);

    float acc[4][6][4];
    #pragma unroll
    for (int i = 0; i < 4; i++)
        #pragma unroll
        for (int j = 0; j < 6; j++)
            #pragma unroll
            for (int q = 0; q < 4; q++) acc[i][j][q] = 0.0f;

    for (int ci0 = 0; ci0 < CIN; ci0 += 32) {
        // halo 18x18, 32 ci = 4 x 16B per pixel
        for (int idx = t; idx < 324 * 4; idx += 256) {
            int ck = idx & 3, pos = idx >> 2;
            int hp = pos / 18, wp = pos % 18;
            int gy = y0 + hp - 1, gx = x0 + wp - 1;
            unsigned dst = ins_base + (unsigned)(pos * PIT + ck * 4) * 4;
            if ((unsigned)gy < 256u && (unsigned)gx < 256u) {
                cpa16(dst, in16 + (size_t)((b << 16) | (gy << 8) | gx) * CIN + ci0 + ck * 8);
            } else {
                *(uint4*)&ins_u[pos * PIT + ck * 4] = make_uint4(0, 0, 0, 0);
            }
        }
        // weights: 9 taps x 96 co, 32 ci = 4 x 16B per row
        for (int idx = t; idx < 9 * 96 * 4; idx += 256) {
            int ck = idx & 3, row = idx >> 2;       // row = tap*96 + co
            int tap = row / 96, co = row % 96;
            cpa16(ws_base + (unsigned)(row * PIT + ck * 4) * 4,
                  w16t + ((size_t)tap * COUT + cohalf * 96 + co) * CIN + ci0 + ck * 8);
        }
        cpa_commit_wait();
        __syncthreads();

        #pragma unroll
        for (int dy = 0; dy < 3; dy++) {
            #pragma unroll
            for (int dx = 0; dx < 3; dx++) {
                const unsigned* wt = ws_u + (dy * 3 + dx) * 96 * PIT;
                #pragma unroll
                for (int s = 0; s < 2; s++) {
                    int cb = s * 8;
                    unsigned a[4][4];
                    #pragma unroll
                    for (int i = 0; i < 4; i++) {
                        int base = (wm * 4 + i + dy) * 18 + dx;
                        a[i][0] = ins_u[(base + g)     * PIT + cb + tg];
                        a[i][1] = ins_u[(base + g + 8) * PIT + cb + tg];
                        a[i][2] = ins_u[(base + g)     * PIT + cb + tg + 4];
                        a[i][3] = ins_u[(base + g + 8) * PIT + cb + tg + 4];
                    }
                    unsigned bfr[6][2];
                    #pragma unroll
                    for (int j = 0; j < 6; j++) {
                        int col = wn * 48 + j * 8 + g;
                        bfr[j][0] = wt[col * PIT + cb + tg];
                        bfr[j][1] = wt[col * PIT + cb + tg + 4];
                    }
                    #pragma unroll
                    for (int i = 0; i < 4; i++)
                        #pragma unroll
                        for (int j = 0; j < 6; j++) mma_f16(acc[i][j], a[i], bfr[j]);
                }
            }
        }
        __syncthreads();
    }

    #pragma unroll
    for (int i = 0; i < 4; i++) {
        int y = y0 + wm * 4 + i;
        #pragma unroll
        for (int j = 0; j < 6; j++) {
            int co = cohalf * 96 + wn * 48 + j * 8 + tg * 2;
            float b0 = bias[co], b1 = bias[co + 1];
            #pragma unroll
            for (int half = 0; half < 2; half++) {
                int x = x0 + g + half * 8;
                size_t base = (size_t)((b << 16) | (y << 8) | x) * COUT + co;
                float v0 = acc[i][j][half * 2]     + b0;
                float v1 = acc[i][j][half * 2 + 1] + b1;
                if (ACT == 1) { v0 = fmaxf(v0, 0.0f); v1 = fmaxf(v1, 0.0f); }
                if (ACT == 2) { v0 = gelu_f(v0); v1 = gelu_f(v1); }
                if (RES) { v0 += res[base]; v1 += res[base + 1]; }
                if (O32) { out32[base] = v0; out32[base + 1] = v1; }
                if (O16) *(__half2*)&out16[base] = __floats2half2_rn(v0, v1);
            }
        }
    }
}

// ---------------------------------------------------------------------------
// Windowed dual attention. One block per (window, head). 64 threads = rows.
// ---------------------------------------------------------------------------
DEV int regio(int wblk, int i) { return (wblk < 31) ? 0 : ((i < 4) ? 1 : 2); }

DEV void attn_pass(const float4 (*K4)[4], const float4 (*V4)[4], const float4 q[4],
                   float lsv, const float* rpb_s, int i1, int j1, int cnt1,
                   int wh, int ww, float4 o[4])
{
    float s[64];
    #pragma unroll
    for (int m = 0; m < 64; m++) {
        const float4* kr = K4[m];
        float d;
        d  = q[0].x * kr[0].x + q[0].y * kr[0].y + q[0].z * kr[0].z + q[0].w * kr[0].w;
        d += q[1].x * kr[1].x + q[1].y * kr[1].y + q[1].z * kr[1].z + q[1].w * kr[1].w;
        d += q[2].x * kr[2].x + q[2].y * kr[2].y + q[2].z * kr[2].z + q[2].w * kr[2].w;
        d += q[3].x * kr[3].x + q[3].y * kr[3].y + q[3].z * kr[3].z + q[3].w * kr[3].w;
        int i2 = m >> 3, j2 = m & 7;
        float rb = rpb_s[(i1 - i2 + 7) * 15 + (j1 - j2 + 7)];
        int cnt2 = regio(wh, i2) * 3 + regio(ww, j2);
        s[m] = d * lsv + rb + ((cnt1 != cnt2) ? -100.0f : 0.0f);
    }
    float mx = s[0];
    #pragma unroll
    for (int m = 1; m < 64; m++) mx = fmaxf(mx, s[m]);
    float sum = 0.0f;
    float4 a0 = make_float4(0, 0, 0, 0), a1 = a0, a2 = a0, a3 = a0;
    #pragma unroll
    for (int m = 0; m < 64; m++) {
        float p = expf(s[m] - mx);
        sum += p;
        const float4* vr = V4[m];
        a0.x += p * vr[0].x; a0.y += p * vr[0].y; a0.z += p * vr[0].z; a0.w += p * vr[0].w;
        a1.x += p * vr[1].x; a1.y += p * vr[1].y; a1.z += p * vr[1].z; a1.w += p * vr[1].w;
        a2.x += p * vr[2].x; a2.y += p * vr[2].y; a2.z += p * vr[2].z; a2.w += p * vr[2].w;
        a3.x += p * vr[3].x; a3.y += p * vr[3].y; a3.z += p * vr[3].z; a3.w += p * vr[3].w;
    }
    float inv = 1.0f / sum;
    o[0] = make_float4(a0.x * inv, a0.y * inv, a0.z * inv, a0.w * inv);
    o[1] = make_float4(a1.x * inv, a1.y * inv, a1.z * inv, a1.w * inv);
    o[2] = make_float4(a2.x * inv, a2.y * inv, a2.z * inv, a2.w * inv);
    o[3] = make_float4(a3.x * inv, a3.y * inv, a3.z * inv, a3.w * inv);
}

__global__ void attn_kernel(const float* __restrict__ qkvx, const float* __restrict__ qkvr,
                            const float* __restrict__ lsp, const float* __restrict__ gat,
                            const float* __restrict__ rpbt, float* __restrict__ out,
                            __half* __restrict__ out16)
{
    __shared__ float4 ks[64][4], vs[64][4], krs[64][4], vrs[64][4];
    __shared__ float rpb_s[225];
    int blk  = blockIdx.x;
    int head = blk % HEADS;
    int widx = blk / HEADS;
    int b  = widx >> 10;
    int nw = widx & 1023;
    int wh = nw >> 5, ww = nw & 31;
    int n  = threadIdx.x;
    int i1 = n >> 3, j1 = n & 7;

    size_t tok = (size_t)((b << 16) | ((wh * 8 + i1) << 8) | (ww * 8 + j1));
    size_t rowbase = tok * 288 + head * 16;

    float4 q[4];
    {
        const float4* qp = (const float4*)(qkvx + rowbase);
        q[0] = qp[0]; q[1] = qp[1]; q[2] = qp[2]; q[3] = qp[3];
        float ss = 0.0f;
        #pragma unroll
        for (int i = 0; i < 4; i++)
            ss += q[i].x * q[i].x + q[i].y * q[i].y + q[i].z * q[i].z + q[i].w * q[i].w;
        float inv = 1.0f / fmaxf(sqrtf(ss), 1e-12f);
        #pragma unroll
        for (int i = 0; i < 4; i++) { q[i].x *= inv; q[i].y *= inv; q[i].z *= inv; q[i].w *= inv; }
    }
    {
        const float4* kp = (const float4*)(qkvx + rowbase + 96);
        float4 kv[4] = {kp[0], kp[1], kp[2], kp[3]};
        float ss = 0.0f;
        #pragma unroll
        for (int i = 0; i < 4; i++)
            ss += kv[i].x * kv[i].x + kv[i].y * kv[i].y + kv[i].z * kv[i].z + kv[i].w * kv[i].w;
        float inv = 1.0f / fmaxf(sqrtf(ss), 1e-12f);
        #pragma unroll
        for (int i = 0; i < 4; i++)
            ks[n][i] = make_float4(kv[i].x * inv, kv[i].y * inv, kv[i].z * inv, kv[i].w * inv);
        const float4* vp = (const float4*)(qkvx + rowbase + 192);
        #pragma unroll
        for (int i = 0; i < 4; i++) vs[n][i] = vp[i];
    }
    {
        const float4* kp = (const float4*)(qkvr + rowbase + 96);
        float4 kv[4] = {kp[0], kp[1], kp[2], kp[3]};
        float ss = 0.0f;
        #pragma unroll
        for (int i = 0; i < 4; i++)
            ss += kv[i].x * kv[i].x + kv[i].y * kv[i].y + kv[i].z * kv[i].z + kv[i].w * kv[i].w;
        float inv = 1.0f / fmaxf(sqrtf(ss), 1e-12f);
        #pragma unroll
        for (int i = 0; i < 4; i++)
            krs[n][i] = make_float4(kv[i].x * inv, kv[i].y * inv, kv[i].z * inv, kv[i].w * inv);
        const float4* vp = (const float4*)(qkvr + rowbase + 192);
        #pragma unroll
        for (int i = 0; i < 4; i++) vrs[n][i] = vp[i];
    }
    for (int idx = n; idx < 225; idx += 64) rpb_s[idx] = rpbt[idx * 6 + head];

    float lsv = expf(fminf(lsp[head], 4.605170185988092f));
    float gv  = 1.0f / (1.0f + expf(-gat[head]));
    int cnt1 = regio(wh, i1) * 3 + regio(ww, j1);
    __syncthreads();

    float4 o1[4], o2[4];
    attn_pass(ks,  vs,  q, lsv, rpb_s, i1, j1, cnt1, wh, ww, o1);
    attn_pass(krs, vrs, q, lsv, rpb_s, i1, j1, cnt1, wh, ww, o2);

    float4* op = (float4*)(out + tok * 96 + head * 16);
    __half2* oh = (__half2*)(out16 + tok * 96 + head * 16);
    float og = 1.0f - gv;
    #pragma unroll
    for (int i = 0; i < 4; i++) {
        float4 v = make_float4(og * o1[i].x + gv * o2[i].x,
                               og * o1[i].y + gv * o2[i].y,
                               og * o1[i].z + gv * o2[i].z,
                               og * o1[i].w + gv * o2[i].w);
        op[i] = v;
        oh[2 * i]     = __floats2half2_rn(v.x, v.y);
        oh[2 * i + 1] = __floats2half2_rn(v.z, v.w);
    }
}

// ---------------------------------------------------------------------------
// Host orchestration
// ---------------------------------------------------------------------------
static int g_attr_done = 0;

extern "C" void kernel_launch(void* const* d_in, const int* in_sizes, int n_in,
                              void* d_out, int out_size)
{
    const float* x       = (const float*)d_in[0];
    const float* ref     = (const float*)d_in[1];
    const float* n1g     = (const float*)d_in[2];
    const float* n1b     = (const float*)d_in[3];
    const float* qkv_w   = (const float*)d_in[4];
    const float* qkv_b   = (const float*)d_in[5];
    const float* lscale  = (const float*)d_in[6];
    const float* gating  = (const float*)d_in[7];
    const float* rpbt    = (const float*)d_in[8];
    const float* trunk_w = (const float*)d_in[9];
    const float* trunk_b = (const float*)d_in[10];
    const float* proj_w  = (const float*)d_in[11];
    const float* proj_b  = (const float*)d_in[12];
    const float* n2g     = (const float*)d_in[13];
    const float* n2b     = (const float*)d_in[14];
    const float* fc1_w   = (const float*)d_in[15];
    const float* fc1_b   = (const float*)d_in[16];
    const float* convm_w = (const float*)d_in[17];
    const float* convm_b = (const float*)d_in[18];
    const float* fc2_w   = (const float*)d_in[19];
    const float* fc2_b   = (const float*)d_in[20];
    float* out = (float*)d_out;

    float *qkvx, *qkvr, *ybuf, *x2;
    __half *ln16, *lnr16, *y16, *t16, *h16, *h16b;
    __half *qkvw16, *projw16, *fc1w16, *fc2w16, *trunkw16, *convmw16;
    cudaGetSymbolAddress((void**)&qkvx, g_qkvx);
    cudaGetSymbolAddress((void**)&qkvr, g_qkvr);
    cudaGetSymbolAddress((void**)&ybuf, g_y);
    cudaGetSymbolAddress((void**)&x2,   g_x2);
    cudaGetSymbolAddress((void**)&ln16, g_ln16);
    cudaGetSymbolAddress((void**)&lnr16,g_lnr16);
    cudaGetSymbolAddress((void**)&y16,  g_y16);
    cudaGetSymbolAddress((void**)&t16,  g_t16);
    cudaGetSymbolAddress((void**)&h16,  g_h16);
    cudaGetSymbolAddress((void**)&h16b, g_h16b);
    cudaGetSymbolAddress((void**)&qkvw16,  g_qkvw16);
    cudaGetSymbolAddress((void**)&projw16, g_projw16);
    cudaGetSymbolAddress((void**)&fc1w16,  g_fc1w16);
    cudaGetSymbolAddress((void**)&fc2w16,  g_fc2w16);
    cudaGetSymbolAddress((void**)&trunkw16,g_trunkw16);
    cudaGetSymbolAddress((void**)&convmw16,g_convmw16);

    const int CONV_SMEM    = (9 * 96 * 20 + 324 * 20) * 4;   // 95040
    const int GEMM_SMEM96  = (128 * 52 + 96 * 52) * 4;       // 46592
    const int GEMM_SMEM192 = (128 * 100 + 96 * 100) * 4;     // 89600

    if (!g_attr_done) {
        cudaFuncSetAttribute(conv_h<96, 96, 1, 0, 0, 1>,   cudaFuncAttributeMaxDynamicSharedMemorySize, CONV_SMEM);
        cudaFuncSetAttribute(conv_h<96, 96, 0, 1, 1, 1>,   cudaFuncAttributeMaxDynamicSharedMemorySize, CONV_SMEM);
        cudaFuncSetAttribute(conv_h<192, 192, 2, 0, 0, 1>, cudaFuncAttributeMaxDynamicSharedMemorySize, CONV_SMEM);
        cudaFuncSetAttribute(gemm_h<96, 0, 0>,  cudaFuncAttributeMaxDynamicSharedMemorySize, GEMM_SMEM96);
        cudaFuncSetAttribute(gemm_h<96, 1, 3>,  cudaFuncAttributeMaxDynamicSharedMemorySize, GEMM_SMEM96);
        cudaFuncSetAttribute(gemm_h<96, 0, 1>,  cudaFuncAttributeMaxDynamicSharedMemorySize, GEMM_SMEM96);
        cudaFuncSetAttribute(gemm_h<192, 0, 2>, cudaFuncAttributeMaxDynamicSharedMemorySize, GEMM_SMEM192);
        g_attr_done = 1;
    }

    // weight conversions (fp32 -> fp16 mirrors)
    tohalf_k<<<(288 * 96 + 255) / 256, 256>>>(qkv_w, qkvw16, 288 * 96);
    tohalf_k<<<(96 * 96 + 255) / 256, 256>>>(proj_w, projw16, 96 * 96);
    tohalf_k<<<(192 * 96 + 255) / 256, 256>>>(fc1_w, fc1w16, 192 * 96);
    tohalf_k<<<(96 * 192 + 255) / 256, 256>>>(fc2_w, fc2w16, 96 * 192);
    tohalfT_k<<<(36 * 96 * 96 + 255) / 256, 256>>>(trunk_w, trunkw16, 96, 96, 36);
    tohalfT_k<<<(9 * 192 * 192 + 255) / 256, 256>>>(convm_w, convmw16, 192, 192, 9);

    ln_kernel<<<TOK / 8, 256>>>(x,   n1g, n1b, ln16,  4);
    ln_kernel<<<TOK / 8, 256>>>(ref, n1g, n1b, lnr16, 4);

    gemm_h<96, 0, 0><<<dim3(TOK / 128, 3), 256, GEMM_SMEM96>>>(ln16,  qkvw16, qkv_b, nullptr, qkvx, nullptr, 0, 288);
    gemm_h<96, 0, 0><<<dim3(TOK / 128, 2), 256, GEMM_SMEM96>>>(lnr16, qkvw16, qkv_b, nullptr, qkvr, nullptr, 1, 288);

    attn_kernel<<<Bb * 1024 * HEADS, 64>>>(qkvx, qkvr, lscale, gating, rpbt, ybuf, y16);

    conv_h<96, 96, 1, 0, 0, 1><<<dim3(16, 16, Bb), 256, CONV_SMEM>>>(y16, trunkw16,              trunk_b,       nullptr, nullptr, t16);
    conv_h<96, 96, 0, 1, 1, 1><<<dim3(16, 16, Bb), 256, CONV_SMEM>>>(t16, trunkw16 + 1 * 82944, trunk_b + 96,  ybuf, ybuf, y16);
    conv_h<96, 96, 1, 0, 0, 1><<<dim3(16, 16, Bb), 256, CONV_SMEM>>>(y16, trunkw16 + 2 * 82944, trunk_b + 192, nullptr, nullptr, t16);
    conv_h<96, 96, 0, 1, 1, 1><<<dim3(16, 16, Bb), 256, CONV_SMEM>>>(t16, trunkw16 + 3 * 82944, trunk_b + 288, ybuf, ybuf, y16);

    gemm_h<96, 0, 1><<<dim3(TOK / 128, 1), 256, GEMM_SMEM96>>>(y16, projw16, proj_b, x, x2, nullptr, 0, 96);

    ln_kernel<<<TOK / 8, 256>>>(x2, n2g, n2b, t16, 0);
    gemm_h<96, 1, 3><<<dim3(TOK / 128, 2), 256, GEMM_SMEM96>>>(t16, fc1w16, fc1_b, nullptr, nullptr, h16, 0, 192);
    conv_h<192, 192, 2, 0, 0, 1><<<dim3(16, 16, Bb * 2), 256, CONV_SMEM>>>(h16, convmw16, convm_b, nullptr, nullptr, h16b);
    gemm_h<192, 0, 2><<<dim3(TOK / 128, 1), 256, GEMM_SMEM192>>>(h16b, fc2w16, fc2_b, x2, out, nullptr, 0, 96);
}

// round 9
// speedup vs baseline: 1.6823x; 1.0612x over previous
#include <cuda_runtime.h>
#include <cuda_fp16.h>
#include <math.h>

// ---------------------------------------------------------------------------
// Problem constants
// ---------------------------------------------------------------------------
constexpr int Bb   = 2;
constexpr int Cc   = 96;
constexpr int HEADS= 6;
constexpr int TOK  = Bb * 256 * 256;          // 131072 tokens

// ---------------------------------------------------------------------------
// Static device scratch
// ---------------------------------------------------------------------------
__device__ float g_y   [TOK * Cc];            // fp32 residual carrier
__device__ float g_x2  [TOK * Cc];

__device__ __half g_qkvx16[TOK * 288];
__device__ __half g_qkvr16[TOK * 288];
__device__ __half g_ln16 [TOK * 96];
__device__ __half g_lnr16[TOK * 96];
__device__ __half g_y16  [TOK * 96];
__device__ __half g_t16  [TOK * 96];
__device__ __half g_h16  [TOK * 192];
__device__ __half g_h16b [TOK * 192];

__device__ __half g_qkvw16[288 * 96];
__device__ __half g_projw16[96 * 96];
__device__ __half g_fc1w16[192 * 96];
__device__ __half g_fc2w16[96 * 192];
__device__ __half g_trunkw16[36 * 96 * 96];   // [layer*9+tap][co][ci]
__device__ __half g_convmw16[9 * 192 * 192];  // [tap][co][ci]

#define DEV __device__ __forceinline__

DEV float gelu_f(float v) { return 0.5f * v * (1.0f + erff(v * 0.70710678118654752f)); }

// D += A(16x16, f16, row) * B(16x8, f16, col), fp32 accum
DEV void mma_f16(float* c, const unsigned* a, const unsigned* b) {
    asm("mma.sync.aligned.m16n8k16.row.col.f32.f16.f16.f32 "
        "{%0,%1,%2,%3}, {%4,%5,%6,%7}, {%8,%9}, {%0,%1,%2,%3};"
        : "+f"(c[0]), "+f"(c[1]), "+f"(c[2]), "+f"(c[3])
        : "r"(a[0]), "r"(a[1]), "r"(a[2]), "r"(a[3]), "r"(b[0]), "r"(b[1]));
}

DEV unsigned sa(const void* p) { return (unsigned)__cvta_generic_to_shared(p); }

DEV void cpa16(unsigned dst, const void* src) {
    asm volatile("cp.async.cg.shared.global [%0], [%1], 16;"
                 :: "r"(dst), "l"(__cvta_generic_to_global(src)));
}
DEV void cpa_commit_wait() {
    asm volatile("cp.async.commit_group;");
    asm volatile("cp.async.wait_group 0;" ::: "memory");
}

// 16 consecutive halves -> 4 float4
DEV void ldh16(const __half* p, float4* o) {
    uint4 u = *(const uint4*)p;
    uint4 v = *(const uint4*)(p + 8);
    const __half2* h0 = (const __half2*)&u;
    const __half2* h1 = (const __half2*)&v;
    float2 a0 = __half22float2(h0[0]), a1 = __half22float2(h0[1]);
    float2 a2 = __half22float2(h0[2]), a3 = __half22float2(h0[3]);
    float2 b0 = __half22float2(h1[0]), b1 = __half22float2(h1[1]);
    float2 b2 = __half22float2(h1[2]), b3 = __half22float2(h1[3]);
    o[0] = make_float4(a0.x, a0.y, a1.x, a1.y);
    o[1] = make_float4(a2.x, a2.y, a3.x, a3.y);
    o[2] = make_float4(b0.x, b0.y, b1.x, b1.y);
    o[3] = make_float4(b2.x, b2.y, b3.x, b3.y);
}

// ---------------------------------------------------------------------------
// Weight conversion kernels
// ---------------------------------------------------------------------------
__global__ void tohalf_k(const float* __restrict__ src, __half* __restrict__ dst, int n)
{
    int i = blockIdx.x * 256 + threadIdx.x;
    if (i < n) dst[i] = __float2half_rn(src[i]);
}

// fp32 [tap][ci][co] -> fp16 [tap][co][ci]
__global__ void tohalfT_k(const float* __restrict__ src, __half* __restrict__ dst,
                          int CI, int CO, int ntap)
{
    int i = blockIdx.x * 256 + threadIdx.x;
    if (i >= ntap * CI * CO) return;
    int ci = i % CI, co = (i / CI) % CO, tap = i / (CI * CO);
    dst[i] = __float2half_rn(src[((size_t)tap * CI + ci) * CO + co]);
}

// ---------------------------------------------------------------------------
// LayerNorm over C=96, optional (+shift,+shift) gather; fp16 output
// ---------------------------------------------------------------------------
__global__ void ln_kernel(const float* __restrict__ in, const float* __restrict__ g,
                          const float* __restrict__ bt, __half* __restrict__ out, int shift)
{
    int gid  = blockIdx.x * blockDim.x + threadIdx.x;
    int tok  = gid >> 5;
    int lane = gid & 31;
    if (tok >= TOK) return;
    int b = tok >> 16, rr = tok & 65535, h = rr >> 8, w = rr & 255;
    const float* src = in + (size_t)((b << 16) | (((h + shift) & 255) << 8) | ((w + shift) & 255)) * 96;
    float v0 = src[lane], v1 = src[lane + 32], v2 = src[lane + 64];
    float s = v0 + v1 + v2;
    #pragma unroll
    for (int o = 16; o > 0; o >>= 1) s += __shfl_xor_sync(0xffffffffu, s, o);
    float mu = s * (1.0f / 96.0f);
    float d0 = v0 - mu, d1 = v1 - mu, d2 = v2 - mu;
    float sq = d0 * d0 + d1 * d1 + d2 * d2;
    #pragma unroll
    for (int o = 16; o > 0; o >>= 1) sq += __shfl_xor_sync(0xffffffffu, sq, o);
    float inv = rsqrtf(sq * (1.0f / 96.0f) + 1e-5f);
    __half* dst = out + (size_t)tok * 96;
    dst[lane]      = __float2half_rn(d0 * inv * g[lane]      + bt[lane]);
    dst[lane + 32] = __float2half_rn(d1 * inv * g[lane + 32] + bt[lane + 32]);
    dst[lane + 64] = __float2half_rn(d2 * inv * g[lane + 64] + bt[lane + 64]);
}

// ---------------------------------------------------------------------------
// Tensor-core GEMM (fp16 m16n8k16), cp.async staging from fp16 mirrors.
// Block: 128 rows x 96 cols, 8 warps (4 Mquad x 2 Nhalf); warp 2x6 frags.
// MODE 0 fp32 plain, 1 proj roll+res fp32, 2 res fp32, 3 fp16 plain.
// ACT 0 none, 1 gelu.
// ---------------------------------------------------------------------------
template<int K, int ACT, int MODE>
__global__ void __launch_bounds__(256) gemm_h(
        const __half* __restrict__ A, const __half* __restrict__ W,
        const float* __restrict__ bias, const float* __restrict__ res,
        float* __restrict__ out, __half* __restrict__ out16, int n0_off, int outN)
{
    constexpr int KP = K / 2;
    constexpr int AP = KP + 4;                  // 52 or 100 (%32 = 20 / 4)
    constexpr int CH = K / 8;                   // 16B chunks per row
    extern __shared__ unsigned smem_u[];
    unsigned* As = smem_u;                      // 128*AP
    unsigned* Ws = smem_u + 128 * AP;           // 96*AP
    int m0 = blockIdx.x * 128;
    int n0 = (blockIdx.y + n0_off) * 96;
    int t  = threadIdx.x;
    int warp = t >> 5, lane = t & 31;
    int wm = warp >> 1, wn = warp & 1;
    int g = lane >> 2, tg = lane & 3;

    unsigned as_base = sa(As), ws_base = sa(Ws);
    #pragma unroll
    for (int i = 0; i < 128 * CH / 256; i++) {
        int idx = t + i * 256;
        int m = idx / CH, c = idx % CH;
        cpa16(as_base + (unsigned)(m * AP + c * 4) * 4, A + (size_t)(m0 + m) * K + c * 8);
    }
    for (int idx = t; idx < 96 * CH; idx += 256) {
        int c = idx / CH, ck = idx % CH;
        cpa16(ws_base + (unsigned)(c * AP + ck * 4) * 4, W + (size_t)(n0 + c) * K + ck * 8);
    }
    cpa_commit_wait();
    __syncthreads();

    float acc[2][6][4];
    #pragma unroll
    for (int i = 0; i < 2; i++)
        #pragma unroll
        for (int j = 0; j < 6; j++)
            #pragma unroll
            for (int q = 0; q < 4; q++) acc[i][j][q] = 0.0f;

    #pragma unroll
    for (int s = 0; s < K / 16; s++) {
        int kb = s * 8;
        unsigned a[2][4];
        #pragma unroll
        for (int i = 0; i < 2; i++) {
            int mb = (wm * 2 + i) * 16;
            a[i][0] = As[(mb + g)     * AP + kb + tg];
            a[i][1] = As[(mb + g + 8) * AP + kb + tg];
            a[i][2] = As[(mb + g)     * AP + kb + tg + 4];
            a[i][3] = As[(mb + g + 8) * AP + kb + tg + 4];
        }
        unsigned b[6][2];
        #pragma unroll
        for (int j = 0; j < 6; j++) {
            int col = wn * 48 + j * 8 + g;
            b[j][0] = Ws[col * AP + kb + tg];
            b[j][1] = Ws[col * AP + kb + tg + 4];
        }
        #pragma unroll
        for (int i = 0; i < 2; i++)
            #pragma unroll
            for (int j = 0; j < 6; j++) mma_f16(acc[i][j], a[i], b[j]);
    }

    #pragma unroll
    for (int i = 0; i < 2; i++) {
        int rb = m0 + (wm * 2 + i) * 16;
        #pragma unroll
        for (int j = 0; j < 6; j++) {
            int c = n0 + wn * 48 + j * 8 + tg * 2;
            #pragma unroll
            for (int half = 0; half < 2; half++) {
                int row = rb + g + half * 8;
                float v0 = acc[i][j][half * 2]     + bias[c];
                float v1 = acc[i][j][half * 2 + 1] + bias[c + 1];
                if (ACT == 1) { v0 = gelu_f(v0); v1 = gelu_f(v1); }
                if (MODE == 0) {
                    out[(size_t)row * outN + c]     = v0;
                    out[(size_t)row * outN + c + 1] = v1;
                } else if (MODE == 1) {
                    int bb = row >> 16, rr = row & 65535, hy = rr >> 8, wx = rr & 255;
                    int tr = (bb << 16) | (((hy + 4) & 255) << 8) | ((wx + 4) & 255);
                    out[(size_t)tr * 96 + c]     = res[(size_t)tr * 96 + c]     + v0;
                    out[(size_t)tr * 96 + c + 1] = res[(size_t)tr * 96 + c + 1] + v1;
                } else if (MODE == 2) {
                    out[(size_t)row * 96 + c]     = res[(size_t)row * 96 + c]     + v0;
                    out[(size_t)row * 96 + c + 1] = res[(size_t)row * 96 + c + 1] + v1;
                } else {
                    *(__half2*)&out16[(size_t)row * outN + c] =
                        __floats2half2_rn(v0, v1);
                }
            }
        }
    }
}

// ---------------------------------------------------------------------------
// Tensor-core 3x3 SAME conv (implicit GEMM, fp16 m16n8k16), cp.async staging.
// Block: 16x16 pixel tile x 96 cout, 256 threads (8 warps: 4 Mquad x 2 Nhalf).
// Halo 18x18 = 324 pos, smem [324][20]; weights [9*96][20] per 32-ci chunk.
// grid = (16, 16, b*(COUT/96)+cohalf). ACT 0/1/2 = none/relu/gelu.
// ---------------------------------------------------------------------------
template<int CIN, int COUT, int ACT, int RES, int O32, int O16>
__global__ void __launch_bounds__(256) conv_h(
        const __half* __restrict__ in16, const __half* __restrict__ w16t,
        const float* __restrict__ bias, const float* __restrict__ res,
        float* __restrict__ out32, __half* __restrict__ out16)
{
    constexpr int PIT = 20;           // kpair pitch (u32), %32 = 20
    constexpr int NH = COUT / 96;
    extern __shared__ unsigned smem_u[];
    unsigned* ws_u  = smem_u;                       // [9*96][PIT]
    unsigned* ins_u = smem_u + 9 * 96 * PIT;        // [324][PIT]

    int x0 = blockIdx.x * 16, y0 = blockIdx.y * 16;
    int zb = blockIdx.z;
    int cohalf = (NH == 1) ? 0 : (zb & 1);
    int b      = (NH == 1) ? zb : (zb >> 1);
    int t  = threadIdx.x;
    int warp = t >> 5, lane = t & 31;
    int wm = warp >> 1, wn = warp & 1;
    int g = lane >> 2, tg = lane & 3;

    unsigned ins_base = sa(ins_u), ws_base = sa(ws_u);

    float acc[4][6][4];
    #pragma unroll
    for (int i = 0; i < 4; i++)
        #pragma unroll
        for (int j = 0; j < 6; j++)
            #pragma unroll
            for (int q = 0; q < 4; q++) acc[i][j][q] = 0.0f;

    for (int ci0 = 0; ci0 < CIN; ci0 += 32) {
        // halo 18x18, 32 ci = 4 x 16B per pixel
        for (int idx = t; idx < 324 * 4; idx += 256) {
            int ck = idx & 3, pos = idx >> 2;
            int hp = pos / 18, wp = pos % 18;
            int gy = y0 + hp - 1, gx = x0 + wp - 1;
            unsigned dst = ins_base + (unsigned)(pos * PIT + ck * 4) * 4;
            if ((unsigned)gy < 256u && (unsigned)gx < 256u) {
                cpa16(dst, in16 + (size_t)((b << 16) | (gy << 8) | gx) * CIN + ci0 + ck * 8);
            } else {
                *(uint4*)&ins_u[pos * PIT + ck * 4] = make_uint4(0, 0, 0, 0);
            }
        }
        // weights: 9 taps x 96 co, 32 ci = 4 x 16B per row
        for (int idx = t; idx < 9 * 96 * 4; idx += 256) {
            int ck = idx & 3, row = idx >> 2;       // row = tap*96 + co
            int tap = row / 96, co = row % 96;
            cpa16(ws_base + (unsigned)(row * PIT + ck * 4) * 4,
                  w16t + ((size_t)tap * COUT + cohalf * 96 + co) * CIN + ci0 + ck * 8);
        }
        cpa_commit_wait();
        __syncthreads();

        #pragma unroll
        for (int dy = 0; dy < 3; dy++) {
            #pragma unroll
            for (int dx = 0; dx < 3; dx++) {
                const unsigned* wt = ws_u + (dy * 3 + dx) * 96 * PIT;
                #pragma unroll
                for (int s = 0; s < 2; s++) {
                    int cb = s * 8;
                    unsigned a[4][4];
                    #pragma unroll
                    for (int i = 0; i < 4; i++) {
                        int base = (wm * 4 + i + dy) * 18 + dx;
                        a[i][0] = ins_u[(base + g)     * PIT + cb + tg];
                        a[i][1] = ins_u[(base + g + 8) * PIT + cb + tg];
                        a[i][2] = ins_u[(base + g)     * PIT + cb + tg + 4];
                        a[i][3] = ins_u[(base + g + 8) * PIT + cb + tg + 4];
                    }
                    unsigned bfr[6][2];
                    #pragma unroll
                    for (int j = 0; j < 6; j++) {
                        int col = wn * 48 + j * 8 + g;
                        bfr[j][0] = wt[col * PIT + cb + tg];
                        bfr[j][1] = wt[col * PIT + cb + tg + 4];
                    }
                    #pragma unroll
                    for (int i = 0; i < 4; i++)
                        #pragma unroll
                        for (int j = 0; j < 6; j++) mma_f16(acc[i][j], a[i], bfr[j]);
                }
            }
        }
        __syncthreads();
    }

    #pragma unroll
    for (int i = 0; i < 4; i++) {
        int y = y0 + wm * 4 + i;
        #pragma unroll
        for (int j = 0; j < 6; j++) {
            int co = cohalf * 96 + wn * 48 + j * 8 + tg * 2;
            float b0 = bias[co], b1 = bias[co + 1];
            #pragma unroll
            for (int half = 0; half < 2; half++) {
                int x = x0 + g + half * 8;
                size_t base = (size_t)((b << 16) | (y << 8) | x) * COUT + co;
                float v0 = acc[i][j][half * 2]     + b0;
                float v1 = acc[i][j][half * 2 + 1] + b1;
                if (ACT == 1) { v0 = fmaxf(v0, 0.0f); v1 = fmaxf(v1, 0.0f); }
                if (ACT == 2) { v0 = gelu_f(v0); v1 = gelu_f(v1); }
                if (RES) { v0 += res[base]; v1 += res[base + 1]; }
                if (O32) { out32[base] = v0; out32[base + 1] = v1; }
                if (O16) *(__half2*)&out16[base] = __floats2half2_rn(v0, v1);
            }
        }
    }
}

// ---------------------------------------------------------------------------
// Windowed dual attention. One block per (window, head). 64 threads = rows.
// qkv inputs fp16; all math fp32.
// ---------------------------------------------------------------------------
DEV int regio(int wblk, int i) { return (wblk < 31) ? 0 : ((i < 4) ? 1 : 2); }

DEV void attn_pass(const float4 (*K4)[4], const float4 (*V4)[4], const float4 q[4],
                   float lsv, const float* rpb_s, int i1, int j1, int cnt1,
                   int wh, int ww, float4 o[4])
{
    float s[64];
    #pragma unroll
    for (int m = 0; m < 64; m++) {
        const float4* kr = K4[m];
        float d;
        d  = q[0].x * kr[0].x + q[0].y * kr[0].y + q[0].z * kr[0].z + q[0].w * kr[0].w;
        d += q[1].x * kr[1].x + q[1].y * kr[1].y + q[1].z * kr[1].z + q[1].w * kr[1].w;
        d += q[2].x * kr[2].x + q[2].y * kr[2].y + q[2].z * kr[2].z + q[2].w * kr[2].w;
        d += q[3].x * kr[3].x + q[3].y * kr[3].y + q[3].z * kr[3].z + q[3].w * kr[3].w;
        int i2 = m >> 3, j2 = m & 7;
        float rb = rpb_s[(i1 - i2 + 7) * 15 + (j1 - j2 + 7)];
        int cnt2 = regio(wh, i2) * 3 + regio(ww, j2);
        s[m] = d * lsv + rb + ((cnt1 != cnt2) ? -100.0f : 0.0f);
    }
    float mx = s[0];
    #pragma unroll
    for (int m = 1; m < 64; m++) mx = fmaxf(mx, s[m]);
    float sum = 0.0f;
    float4 a0 = make_float4(0, 0, 0, 0), a1 = a0, a2 = a0, a3 = a0;
    #pragma unroll
    for (int m = 0; m < 64; m++) {
        float p = expf(s[m] - mx);
        sum += p;
        const float4* vr = V4[m];
        a0.x += p * vr[0].x; a0.y += p * vr[0].y; a0.z += p * vr[0].z; a0.w += p * vr[0].w;
        a1.x += p * vr[1].x; a1.y += p * vr[1].y; a1.z += p * vr[1].z; a1.w += p * vr[1].w;
        a2.x += p * vr[2].x; a2.y += p * vr[2].y; a2.z += p * vr[2].z; a2.w += p * vr[2].w;
        a3.x += p * vr[3].x; a3.y += p * vr[3].y; a3.z += p * vr[3].z; a3.w += p * vr[3].w;
    }
    float inv = 1.0f / sum;
    o[0] = make_float4(a0.x * inv, a0.y * inv, a0.z * inv, a0.w * inv);
    o[1] = make_float4(a1.x * inv, a1.y * inv, a1.z * inv, a1.w * inv);
    o[2] = make_float4(a2.x * inv, a2.y * inv, a2.z * inv, a2.w * inv);
    o[3] = make_float4(a3.x * inv, a3.y * inv, a3.z * inv, a3.w * inv);
}

__global__ void attn_kernel(const __half* __restrict__ qkvx, const __half* __restrict__ qkvr,
                            const float* __restrict__ lsp, const float* __restrict__ gat,
                            const float* __restrict__ rpbt, float* __restrict__ out,
                            __half* __restrict__ out16)
{
    __shared__ float4 ks[64][4], vs[64][4], krs[64][4], vrs[64][4];
    __shared__ float rpb_s[225];
    int blk  = blockIdx.x;
    int head = blk % HEADS;
    int widx = blk / HEADS;
    int b  = widx >> 10;
    int nw = widx & 1023;
    int wh = nw >> 5, ww = nw & 31;
    int n  = threadIdx.x;
    int i1 = n >> 3, j1 = n & 7;

    size_t tok = (size_t)((b << 16) | ((wh * 8 + i1) << 8) | (ww * 8 + j1));
    size_t rowbase = tok * 288 + head * 16;

    float4 q[4];
    {
        ldh16(qkvx + rowbase, q);
        float ss = 0.0f;
        #pragma unroll
        for (int i = 0; i < 4; i++)
            ss += q[i].x * q[i].x + q[i].y * q[i].y + q[i].z * q[i].z + q[i].w * q[i].w;
        float inv = 1.0f / fmaxf(sqrtf(ss), 1e-12f);
        #pragma unroll
        for (int i = 0; i < 4; i++) { q[i].x *= inv; q[i].y *= inv; q[i].z *= inv; q[i].w *= inv; }
    }
    {
        float4 kv[4];
        ldh16(qkvx + rowbase + 96, kv);
        float ss = 0.0f;
        #pragma unroll
        for (int i = 0; i < 4; i++)
            ss += kv[i].x * kv[i].x + kv[i].y * kv[i].y + kv[i].z * kv[i].z + kv[i].w * kv[i].w;
        float inv = 1.0f / fmaxf(sqrtf(ss), 1e-12f);
        #pragma unroll
        for (int i = 0; i < 4; i++)
            ks[n][i] = make_float4(kv[i].x * inv, kv[i].y * inv, kv[i].z * inv, kv[i].w * inv);
        float4 vv[4];
        ldh16(qkvx + rowbase + 192, vv);
        #pragma unroll
        for (int i = 0; i < 4; i++) vs[n][i] = vv[i];
    }
    {
        float4 kv[4];
        ldh16(qkvr + rowbase + 96, kv);
        float ss = 0.0f;
        #pragma unroll
        for (int i = 0; i < 4; i++)
            ss += kv[i].x * kv[i].x + kv[i].y * kv[i].y + kv[i].z * kv[i].z + kv[i].w * kv[i].w;
        float inv = 1.0f / fmaxf(sqrtf(ss), 1e-12f);
        #pragma unroll
        for (int i = 0; i < 4; i++)
            krs[n][i] = make_float4(kv[i].x * inv, kv[i].y * inv, kv[i].z * inv, kv[i].w * inv);
        float4 vv[4];
        ldh16(qkvr + rowbase + 192, vv);
        #pragma unroll
        for (int i = 0; i < 4; i++) vrs[n][i] = vv[i];
    }
    for (int idx = n; idx < 225; idx += 64) rpb_s[idx] = rpbt[idx * 6 + head];

    float lsv = expf(fminf(lsp[head], 4.605170185988092f));
    float gv  = 1.0f / (1.0f + expf(-gat[head]));
    int cnt1 = regio(wh, i1) * 3 + regio(ww, j1);
    __syncthreads();

    float4 o1[4], o2[4];
    attn_pass(ks,  vs,  q, lsv, rpb_s, i1, j1, cnt1, wh, ww, o1);
    attn_pass(krs, vrs, q, lsv, rpb_s, i1, j1, cnt1, wh, ww, o2);

    float4* op = (float4*)(out + tok * 96 + head * 16);
    __half2* oh = (__half2*)(out16 + tok * 96 + head * 16);
    float og = 1.0f - gv;
    #pragma unroll
    for (int i = 0; i < 4; i++) {
        float4 v = make_float4(og * o1[i].x + gv * o2[i].x,
                               og * o1[i].y + gv * o2[i].y,
                               og * o1[i].z + gv * o2[i].z,
                               og * o1[i].w + gv * o2[i].w);
        op[i] = v;
        oh[2 * i]     = __floats2half2_rn(v.x, v.y);
        oh[2 * i + 1] = __floats2half2_rn(v.z, v.w);
    }
}

// ---------------------------------------------------------------------------
// Host orchestration
// ---------------------------------------------------------------------------
static int g_attr_done = 0;

extern "C" void kernel_launch(void* const* d_in, const int* in_sizes, int n_in,
                              void* d_out, int out_size)
{
    const float* x       = (const float*)d_in[0];
    const float* ref     = (const float*)d_in[1];
    const float* n1g     = (const float*)d_in[2];
    const float* n1b     = (const float*)d_in[3];
    const float* qkv_w   = (const float*)d_in[4];
    const float* qkv_b   = (const float*)d_in[5];
    const float* lscale  = (const float*)d_in[6];
    const float* gating  = (const float*)d_in[7];
    const float* rpbt    = (const float*)d_in[8];
    const float* trunk_w = (const float*)d_in[9];
    const float* trunk_b = (const float*)d_in[10];
    const float* proj_w  = (const float*)d_in[11];
    const float* proj_b  = (const float*)d_in[12];
    const float* n2g     = (const float*)d_in[13];
    const float* n2b     = (const float*)d_in[14];
    const float* fc1_w   = (const float*)d_in[15];
    const float* fc1_b   = (const float*)d_in[16];
    const float* convm_w = (const float*)d_in[17];
    const float* convm_b = (const float*)d_in[18];
    const float* fc2_w   = (const float*)d_in[19];
    const float* fc2_b   = (const float*)d_in[20];
    float* out = (float*)d_out;

    float *ybuf, *x2;
    __half *qkvx16, *qkvr16, *ln16, *lnr16, *y16, *t16, *h16, *h16b;
    __half *qkvw16, *projw16, *fc1w16, *fc2w16, *trunkw16, *convmw16;
    cudaGetSymbolAddress((void**)&ybuf, g_y);
    cudaGetSymbolAddress((void**)&x2,   g_x2);
    cudaGetSymbolAddress((void**)&qkvx16, g_qkvx16);
    cudaGetSymbolAddress((void**)&qkvr16, g_qkvr16);
    cudaGetSymbolAddress((void**)&ln16, g_ln16);
    cudaGetSymbolAddress((void**)&lnr16,g_lnr16);
    cudaGetSymbolAddress((void**)&y16,  g_y16);
    cudaGetSymbolAddress((void**)&t16,  g_t16);
    cudaGetSymbolAddress((void**)&h16,  g_h16);
    cudaGetSymbolAddress((void**)&h16b, g_h16b);
    cudaGetSymbolAddress((void**)&qkvw16,  g_qkvw16);
    cudaGetSymbolAddress((void**)&projw16, g_projw16);
    cudaGetSymbolAddress((void**)&fc1w16,  g_fc1w16);
    cudaGetSymbolAddress((void**)&fc2w16,  g_fc2w16);
    cudaGetSymbolAddress((void**)&trunkw16,g_trunkw16);
    cudaGetSymbolAddress((void**)&convmw16,g_convmw16);

    const int CONV_SMEM    = (9 * 96 * 20 + 324 * 20) * 4;   // 95040
    const int GEMM_SMEM96  = (128 * 52 + 96 * 52) * 4;       // 46592
    const int GEMM_SMEM192 = (128 * 100 + 96 * 100) * 4;     // 89600

    if (!g_attr_done) {
        cudaFuncSetAttribute(conv_h<96, 96, 1, 0, 0, 1>,   cudaFuncAttributeMaxDynamicSharedMemorySize, CONV_SMEM);
        cudaFuncSetAttribute(conv_h<96, 96, 0, 1, 1, 1>,   cudaFuncAttributeMaxDynamicSharedMemorySize, CONV_SMEM);
        cudaFuncSetAttribute(conv_h<192, 192, 2, 0, 0, 1>, cudaFuncAttributeMaxDynamicSharedMemorySize, CONV_SMEM);
        cudaFuncSetAttribute(gemm_h<96, 0, 3>,  cudaFuncAttributeMaxDynamicSharedMemorySize, GEMM_SMEM96);
        cudaFuncSetAttribute(gemm_h<96, 1, 3>,  cudaFuncAttributeMaxDynamicSharedMemorySize, GEMM_SMEM96);
        cudaFuncSetAttribute(gemm_h<96, 0, 1>,  cudaFuncAttributeMaxDynamicSharedMemorySize, GEMM_SMEM96);
        cudaFuncSetAttribute(gemm_h<192, 0, 2>, cudaFuncAttributeMaxDynamicSharedMemorySize, GEMM_SMEM192);
        g_attr_done = 1;
    }

    // weight conversions (fp32 -> fp16 mirrors)
    tohalf_k<<<(288 * 96 + 255) / 256, 256>>>(qkv_w, qkvw16, 288 * 96);
    tohalf_k<<<(96 * 96 + 255) / 256, 256>>>(proj_w, projw16, 96 * 96);
    tohalf_k<<<(192 * 96 + 255) / 256, 256>>>(fc1_w, fc1w16, 192 * 96);
    tohalf_k<<<(96 * 192 + 255) / 256, 256>>>(fc2_w, fc2w16, 96 * 192);
    tohalfT_k<<<(36 * 96 * 96 + 255) / 256, 256>>>(trunk_w, trunkw16, 96, 96, 36);
    tohalfT_k<<<(9 * 192 * 192 + 255) / 256, 256>>>(convm_w, convmw16, 192, 192, 9);

    ln_kernel<<<TOK / 8, 256>>>(x,   n1g, n1b, ln16,  4);
    ln_kernel<<<TOK / 8, 256>>>(ref, n1g, n1b, lnr16, 4);

    gemm_h<96, 0, 3><<<dim3(TOK / 128, 3), 256, GEMM_SMEM96>>>(ln16,  qkvw16, qkv_b, nullptr, nullptr, qkvx16, 0, 288);
    gemm_h<96, 0, 3><<<dim3(TOK / 128, 2), 256, GEMM_SMEM96>>>(lnr16, qkvw16, qkv_b, nullptr, nullptr, qkvr16, 1, 288);

    attn_kernel<<<Bb * 1024 * HEADS, 64>>>(qkvx16, qkvr16, lscale, gating, rpbt, ybuf, y16);

    conv_h<96, 96, 1, 0, 0, 1><<<dim3(16, 16, Bb), 256, CONV_SMEM>>>(y16, trunkw16,              trunk_b,       nullptr, nullptr, t16);
    conv_h<96, 96, 0, 1, 1, 1><<<dim3(16, 16, Bb), 256, CONV_SMEM>>>(t16, trunkw16 + 1 * 82944, trunk_b + 96,  ybuf, ybuf, y16);
    conv_h<96, 96, 1, 0, 0, 1><<<dim3(16, 16, Bb), 256, CONV_SMEM>>>(y16, trunkw16 + 2 * 82944, trunk_b + 192, nullptr, nullptr, t16);
    conv_h<96, 96, 0, 1, 1, 1><<<dim3(16, 16, Bb), 256, CONV_SMEM>>>(t16, trunkw16 + 3 * 82944, trunk_b + 288, ybuf, ybuf, y16);

    gemm_h<96, 0, 1><<<dim3(TOK / 128, 1), 256, GEMM_SMEM96>>>(y16, projw16, proj_b, x, x2, nullptr, 0, 96);

    ln_kernel<<<TOK / 8, 256>>>(x2, n2g, n2b, t16, 0);
    gemm_h<96, 1, 3><<<dim3(TOK / 128, 2), 256, GEMM_SMEM96>>>(t16, fc1w16, fc1_b, nullptr, nullptr, h16, 0, 192);
    conv_h<192, 192, 2, 0, 0, 1><<<dim3(16, 16, Bb * 2), 256, CONV_SMEM>>>(h16, convmw16, convm_b, nullptr, nullptr, h16b);
    gemm_h<192, 0, 2><<<dim3(TOK / 128, 1), 256, GEMM_SMEM192>>>(h16b, fc2w16, fc2_b, x2, out, nullptr, 0, 96);
}